// round 10
// baseline (speedup 1.0000x reference)
#include <cuda_runtime.h>
#include <cuda_fp16.h>

#define NVOX 2097152u            // 128^3
#define PLANE 16384              // 128*128
#define CH 32                    // output z-planes per block (z-chunking)

// Scratch: [t*2+n][c(13)][z][y][x] fp16. c=0..11: mind = ssd - min; c=12: mind_var.
// 2*2*13*128^3 halfs = 218 MB
__device__ __half g_ssd[(size_t)2 * 2 * 13 * NVOX];
__device__ float g_msum[2] = {0.f, 0.f};   // finish_kernel re-zeroes after read
__device__ float g_loss = 0.f;

// emit outputs for plane zo given the two z-partial arrays (a + b = full 3-plane sum)
__device__ __forceinline__ void emit(int zo, const float* __restrict__ a,
                                     const float* __restrict__ b,
                                     __half* __restrict__ outBase, float& mvsum)
{
    float v[12];
    #pragma unroll
    for (int c = 0; c < 12; ++c) v[c] = (a[c] + b[c]) * (1.f / 27.f);
    float mn = fminf(fminf(fminf(v[0],v[1]),fminf(v[2],v[3])),
                     fminf(fminf(fminf(v[4],v[5]),fminf(v[6],v[7])),
                           fminf(fminf(v[8],v[9]),fminf(v[10],v[11]))));
    float sm = ((v[0]+v[1])+(v[2]+v[3])) + ((v[4]+v[5])+(v[6]+v[7]))
             + ((v[8]+v[9])+(v[10]+v[11]));
    float mv = sm * (1.f/12.f) - mn;
    __half* o = outBase + (size_t)zo * PLANE;
    #pragma unroll
    for (int c = 0; c < 12; ++c) o[(size_t)c * NVOX] = __float2half_rn(v[c] - mn);
    o[(size_t)12 * NVOX] = __float2half_rn(mv);
    mvsum += mv;
}

__global__ __launch_bounds__(256)
void ssd_kernel(const float* __restrict__ pred, const float* __restrict__ targ)
{
    const int x  = threadIdx.x;           // 0..127
    const int ty = threadIdx.y;           // 0..1
    const int y0 = blockIdx.x * 2;
    const int zc = blockIdx.y;            // z chunk
    const int tn = blockIdx.z;            // t*2+n
    const int t  = tn >> 1;
    const int n  = tn & 1;

    const int z0 = zc * CH, z1 = z0 + CH;
    const int zlo = max(z0 - 1, 0);
    const int zhi = min(z1, 127);

    const float* img = (t == 0 ? pred : targ) + (size_t)n * NVOX;
    __half* outBase = g_ssd + (size_t)tn * 13u * NVOX
                    + (size_t)(y0 + ty) * 128 + x;

    __shared__ float  simg[5][8][128];
    __shared__ float4 bnd[2][4][2][3];    // [ty][warp][0=lane0 / 1=lane31][12 floats]
    __shared__ float  red[256];

    const int lin  = ty * 128 + x;
    const int w    = x >> 5;              // warp-in-row 0..3
    const int lane = x & 31;

    // preload planes zlo-2 .. zlo+1 (z edge-clamped) straight into smem
    for (int q = zlo - 2; q <= zlo + 1; ++q) {
        const int slot = (q + 10) % 5;
        const float* src = img + (size_t)min(max(q, 0), 127) * PLANE;
        #pragma unroll
        for (int k = 0; k < 4; ++k) {
            int e = lin + k * 256;
            int row = e >> 7, xx = e & 127;
            int gy = min(max(y0 - 3 + row, 0), 127);
            simg[slot][row][xx] = src[gy * 128 + xx];
        }
    }
    // prefetch plane zlo+2 into registers (first step stores it)
    float pf[4];
    {
        const float* src = img + (size_t)min(zlo + 2, 127) * PLANE;
        #pragma unroll
        for (int k = 0; k < 4; ++k) {
            int e = lin + k * 256;
            int row = e >> 7, xx = e & 127;
            int gy = min(max(y0 - 3 + row, 0), 127);
            pf[k] = src[gy * 128 + xx];
        }
    }

    const int xm2 = max(x - 2, 0), xp2 = min(x + 2, 127);
    const int gy0 = y0 + ty;

    float prev[12], pair[12];             // s(zp-1), s(zp-2)+s(zp-1)
    float mvsum = 0.f;

    for (int zp = zlo; zp <= zhi; ++zp) {
        // STS plane zp+2 (prefetched), then prefetch plane zp+3
        {
            const int slot = (zp + 2) % 5;
            #pragma unroll
            for (int k = 0; k < 4; ++k) {
                int e = lin + k * 256;
                int row = e >> 7, xx = e & 127;
                simg[slot][row][xx] = pf[k];
            }
        }
        {
            const float* src = img + (size_t)min(zp + 3, 127) * PLANE;
            #pragma unroll
            for (int k = 0; k < 4; ++k) {
                int e = lin + k * 256;
                int row = e >> 7, xx = e & 127;
                int gy = min(max(y0 - 3 + row, 0), 127);
                pf[k] = src[gy * 128 + xx];
            }
        }
        __syncthreads();

        const float* Pzm = &simg[(zp + 3) % 5][0][0];   // plane zp-2 (clamped)
        const float* Pzc = &simg[ zp      % 5][0][0];   // plane zp
        const float* Pzp = &simg[(zp + 2) % 5][0][0];   // plane zp+2 (clamped)

        float ys[12];
        #pragma unroll
        for (int c = 0; c < 12; ++c) ys[c] = 0.f;

        #pragma unroll
        for (int dy = -1; dy <= 1; ++dy) {
            int ly = min(max(gy0 + dy, 0), 127);
            int r  = (ly - y0 + 3) * 128;
            int rm = (max(ly - 2, 0)   - y0 + 3) * 128;
            int rp = (min(ly + 2, 127) - y0 + 3) * 128;
            float V0 = Pzm[r  + x];      // z-2
            float V1 = Pzc[r  + xm2];    // x-2
            float V2 = Pzc[rm + x];      // y-2
            float V3 = Pzc[r  + xp2];    // x+2
            float V4 = Pzp[r  + x];      // z+2
            float V5 = Pzc[rp + x];      // y+2
            float d;
            d = V1 - V0; ys[0]  += d*d;
            d = V2 - V0; ys[1]  += d*d;
            d = V2 - V1; ys[2]  += d*d;
            d = V3 - V0; ys[3]  += d*d;
            d = V3 - V2; ys[4]  += d*d;
            d = V4 - V1; ys[5]  += d*d;
            d = V4 - V2; ys[6]  += d*d;
            d = V4 - V3; ys[7]  += d*d;
            d = V5 - V0; ys[8]  += d*d;
            d = V5 - V1; ys[9]  += d*d;
            d = V5 - V3; ys[10] += d*d;
            d = V5 - V4; ys[11] += d*d;
        }

        // publish warp-boundary lanes for cross-warp x-neighbors
        if (lane == 0) {
            bnd[ty][w][0][0] = make_float4(ys[0], ys[1], ys[2],  ys[3]);
            bnd[ty][w][0][1] = make_float4(ys[4], ys[5], ys[6],  ys[7]);
            bnd[ty][w][0][2] = make_float4(ys[8], ys[9], ys[10], ys[11]);
        } else if (lane == 31) {
            bnd[ty][w][1][0] = make_float4(ys[0], ys[1], ys[2],  ys[3]);
            bnd[ty][w][1][1] = make_float4(ys[4], ys[5], ys[6],  ys[7]);
            bnd[ty][w][1][2] = make_float4(ys[8], ys[9], ys[10], ys[11]);
        }
        __syncthreads();

        // x-sum via intra-warp shuffles + boundary fixups
        float up[12], dn[12];
        #pragma unroll
        for (int c = 0; c < 12; ++c) {
            up[c] = __shfl_up_sync(0xffffffffu, ys[c], 1);
            dn[c] = __shfl_down_sync(0xffffffffu, ys[c], 1);
        }
        if (lane == 0) {
            if (w > 0) {
                float4 a = bnd[ty][w-1][1][0], b = bnd[ty][w-1][1][1], e = bnd[ty][w-1][1][2];
                up[0]=a.x; up[1]=a.y; up[2] =a.z; up[3] =a.w;
                up[4]=b.x; up[5]=b.y; up[6] =b.z; up[7] =b.w;
                up[8]=e.x; up[9]=e.y; up[10]=e.z; up[11]=e.w;
            } else {
                #pragma unroll
                for (int c = 0; c < 12; ++c) up[c] = ys[c];   // x=0 clamp
            }
        }
        if (lane == 31) {
            if (w < 3) {
                float4 a = bnd[ty][w+1][0][0], b = bnd[ty][w+1][0][1], e = bnd[ty][w+1][0][2];
                dn[0]=a.x; dn[1]=a.y; dn[2] =a.z; dn[3] =a.w;
                dn[4]=b.x; dn[5]=b.y; dn[6] =b.z; dn[7] =b.w;
                dn[8]=e.x; dn[9]=e.y; dn[10]=e.z; dn[11]=e.w;
            } else {
                #pragma unroll
                for (int c = 0; c < 12; ++c) dn[c] = ys[c];   // x=127 clamp
            }
        }
        float s[12];
        #pragma unroll
        for (int c = 0; c < 12; ++c) s[c] = up[c] + ys[c] + dn[c];

        // rolling z window
        if (zp == zlo) {
            #pragma unroll
            for (int c = 0; c < 12; ++c) { prev[c] = s[c]; pair[c] = s[c] + s[c]; }
            // pair = 2*s only meaningful for z0==0 (virtual plane -1 == plane 0);
            // for z0>0 it is a placeholder never read before being overwritten.
        } else {
            const int zo = zp - 1;
            if (zo >= z0) emit(zo, pair, s, outBase, mvsum);
            #pragma unroll
            for (int c = 0; c < 12; ++c) { pair[c] = prev[c] + s[c]; prev[c] = s[c]; }
        }
    }
    if (z1 == 128) {
        // out(127): s(126)+s(127)+s(128), s(128)=s(127)  ->  pair + prev
        emit(127, pair, prev, outBase, mvsum);
    }

    // block-reduce mind_var partial sum
    red[lin] = mvsum;
    __syncthreads();
    for (int off = 128; off > 0; off >>= 1) {
        if (lin < off) red[lin] += red[lin + off];
        __syncthreads();
    }
    if (lin == 0) atomicAdd(&g_msum[t], red[0]);
}

__global__ __launch_bounds__(256)
void loss_kernel()
{
    // each thread handles 8 voxel-pairs; mind precomputed, mind_var at channel 12
    const unsigned i8 = blockIdx.x * 256u + threadIdx.x;   // 0 .. 2*NVOX/8-1
    const float mP = g_msum[0] * (1.f / 4194304.f);
    const float mT = g_msum[1] * (1.f / 4194304.f);

    const unsigned nn = i8 >> 18;                 // NVOX/8 = 2^18
    const unsigned s8 = i8 & ((NVOX / 8u) - 1u);

    const uint4* bp = (const uint4*)g_ssd + (size_t)nn       * 13u * (NVOX/8u) + s8;
    const uint4* bt = (const uint4*)g_ssd + (size_t)(2 + nn) * 13u * (NVOX/8u) + s8;

    uint4 vp[13], vt[13];
    #pragma unroll
    for (int c = 0; c < 13; ++c) vp[c] = bp[(size_t)c * (NVOX/8u)];
    #pragma unroll
    for (int c = 0; c < 13; ++c) vt[c] = bt[(size_t)c * (NVOX/8u)];

    const __half2* hp = (const __half2*)vp;   // hp[c*4 + j]
    const __half2* ht = (const __half2*)vt;

    const __half2 loP = __float2half2_rn(0.001f * mP);
    const __half2 hiP = __float2half2_rn(1000.f * mP);
    const __half2 loT = __float2half2_rn(0.001f * mT);
    const __half2 hiT = __float2half2_rn(1000.f * mT);

    float acc = 0.f;
    #pragma unroll
    for (int j = 0; j < 4; ++j) {
        __half2 mvP = __hmin2(__hmax2(hp[12*4 + j], loP), hiP);
        __half2 mvT = __hmin2(__hmax2(ht[12*4 + j], loT), hiT);
        __half2 nivP = __hneg2(h2rcp(mvP));
        __half2 nivT = __hneg2(h2rcp(mvT));
        #pragma unroll
        for (int c = 0; c < 12; ++c) {
            __half2 eP = h2exp(__hmul2(hp[c*4 + j], nivP));
            __half2 eT = h2exp(__hmul2(ht[c*4 + j], nivT));
            float2 d = __half22float2(__hsub2(eP, eT));
            acc += d.x * d.x + d.y * d.y;
        }
    }

    __shared__ float red[256];
    red[threadIdx.x] = acc;
    __syncthreads();
    for (int off = 128; off > 0; off >>= 1) {
        if (threadIdx.x < off) red[threadIdx.x] += red[threadIdx.x + off];
        __syncthreads();
    }
    if (threadIdx.x == 0) atomicAdd(&g_loss, red[0]);
}

__global__ void finish_kernel(float* __restrict__ out)
{
    out[0] = g_loss * (1.f / 50331648.f);
    // reset accumulators for the next graph replay
    g_loss = 0.f; g_msum[0] = 0.f; g_msum[1] = 0.f;
}

extern "C" void kernel_launch(void* const* d_in, const int* in_sizes, int n_in,
                              void* d_out, int out_size)
{
    const float* pred = (const float*)d_in[0];
    const float* targ = (const float*)d_in[1];

    ssd_kernel<<<dim3(64, 128 / CH, 4), dim3(128, 2)>>>(pred, targ);
    loss_kernel<<<2048, 256>>>();
    finish_kernel<<<1, 1>>>((float*)d_out);
}

// round 11
// speedup vs baseline: 1.1486x; 1.1486x over previous
#include <cuda_runtime.h>
#include <cuda_fp16.h>

#define NVOX 2097152u            // 128^3
#define PLANE 16384              // 128*128
#define CH 32                    // output z-planes per block (z-chunking)

// Scratch: [t*2+n][c(13)][z][y][x] fp16. c=0..11: mind = ssd - min; c=12: mind_var.
// 2*2*13*128^3 halfs = 218 MB
__device__ __half g_ssd[(size_t)2 * 2 * 13 * NVOX];
__device__ float g_msum[2] = {0.f, 0.f};   // finish_kernel re-zeroes after read
__device__ float g_loss = 0.f;

// emit outputs for plane zo given the two z-partial arrays (a + b = full 3-plane sum)
__device__ __forceinline__ void emit(int zo, const float* __restrict__ a,
                                     const float* __restrict__ b,
                                     __half* __restrict__ outBase, float& mvsum)
{
    float v[12];
    #pragma unroll
    for (int c = 0; c < 12; ++c) v[c] = (a[c] + b[c]) * (1.f / 27.f);
    float mn = fminf(fminf(fminf(v[0],v[1]),fminf(v[2],v[3])),
                     fminf(fminf(fminf(v[4],v[5]),fminf(v[6],v[7])),
                           fminf(fminf(v[8],v[9]),fminf(v[10],v[11]))));
    float sm = ((v[0]+v[1])+(v[2]+v[3])) + ((v[4]+v[5])+(v[6]+v[7]))
             + ((v[8]+v[9])+(v[10]+v[11]));
    float mv = sm * (1.f/12.f) - mn;
    __half* o = outBase + (size_t)zo * PLANE;
    #pragma unroll
    for (int c = 0; c < 12; ++c) o[(size_t)c * NVOX] = __float2half_rn(v[c] - mn);
    o[(size_t)12 * NVOX] = __float2half_rn(mv);
    mvsum += mv;
}

__global__ __launch_bounds__(256)
void ssd_kernel(const float* __restrict__ pred, const float* __restrict__ targ)
{
    const int x  = threadIdx.x;           // 0..127
    const int ty = threadIdx.y;           // 0..1
    const int y0 = blockIdx.x * 2;
    const int zc = blockIdx.y;            // z chunk
    const int tn = blockIdx.z;            // t*2+n
    const int t  = tn >> 1;
    const int n  = tn & 1;

    const int z0 = zc * CH, z1 = z0 + CH;
    const int zlo = max(z0 - 1, 0);
    const int zhi = min(z1, 127);

    const float* img = (t == 0 ? pred : targ) + (size_t)n * NVOX;
    __half* outBase = g_ssd + (size_t)tn * 13u * NVOX
                    + (size_t)(y0 + ty) * 128 + x;

    __shared__ float  simg[5][8][128];
    __shared__ float4 ysb[2][128][3];
    __shared__ float  red[256];

    const int lin = ty * 128 + x;

    // preload planes zlo-2 .. zlo+1 (z edge-clamped) straight into smem
    for (int q = zlo - 2; q <= zlo + 1; ++q) {
        const int slot = (q + 10) % 5;
        const float* src = img + (size_t)min(max(q, 0), 127) * PLANE;
        #pragma unroll
        for (int k = 0; k < 4; ++k) {
            int e = lin + k * 256;
            int row = e >> 7, xx = e & 127;
            int gy = min(max(y0 - 3 + row, 0), 127);
            simg[slot][row][xx] = src[gy * 128 + xx];
        }
    }
    // prefetch plane zlo+2 into registers (first step stores it)
    float pf[4];
    {
        const float* src = img + (size_t)min(zlo + 2, 127) * PLANE;
        #pragma unroll
        for (int k = 0; k < 4; ++k) {
            int e = lin + k * 256;
            int row = e >> 7, xx = e & 127;
            int gy = min(max(y0 - 3 + row, 0), 127);
            pf[k] = src[gy * 128 + xx];
        }
    }

    const int xm2 = max(x - 2, 0), xp2 = min(x + 2, 127);
    const int xm1 = max(x - 1, 0), xp1 = min(x + 1, 127);
    const int gy0 = y0 + ty;

    // hoist z-invariant clamped y-row offsets (per dy = -1,0,1)
    int rA[3], rmA[3], rpA[3];
    #pragma unroll
    for (int k = 0; k < 3; ++k) {
        int ly = min(max(gy0 + (k - 1), 0), 127);
        rA[k]  = (ly - y0 + 3) * 128 + x;
        rmA[k] = (max(ly - 2, 0)   - y0 + 3) * 128 + x;
        rpA[k] = (min(ly + 2, 127) - y0 + 3) * 128 + x;
    }

    float prev[12], pair[12];             // s(zp-1), s(zp-2)+s(zp-1)
    float mvsum = 0.f;

    for (int zp = zlo; zp <= zhi; ++zp) {
        // STS plane zp+2 (prefetched), then prefetch plane zp+3
        {
            const int slot = (zp + 2) % 5;
            #pragma unroll
            for (int k = 0; k < 4; ++k) {
                int e = lin + k * 256;
                int row = e >> 7, xx = e & 127;
                simg[slot][row][xx] = pf[k];
            }
        }
        {
            const float* src = img + (size_t)min(zp + 3, 127) * PLANE;
            #pragma unroll
            for (int k = 0; k < 4; ++k) {
                int e = lin + k * 256;
                int row = e >> 7, xx = e & 127;
                int gy = min(max(y0 - 3 + row, 0), 127);
                pf[k] = src[gy * 128 + xx];
            }
        }
        __syncthreads();

        const float* Pzm = &simg[(zp + 3) % 5][0][0];   // plane zp-2 (clamped)
        const float* Pzc = &simg[ zp      % 5][0][0];   // plane zp
        const float* Pzp = &simg[(zp + 2) % 5][0][0];   // plane zp+2 (clamped)

        float ys[12];
        #pragma unroll
        for (int c = 0; c < 12; ++c) ys[c] = 0.f;

        #pragma unroll
        for (int k = 0; k < 3; ++k) {
            const int r  = rA[k];
            float V0 = Pzm[r];                 // z-2
            float V1 = Pzc[r - x + xm2];       // x-2
            float V2 = Pzc[rmA[k]];            // y-2
            float V3 = Pzc[r - x + xp2];       // x+2
            float V4 = Pzp[r];                 // z+2
            float V5 = Pzc[rpA[k]];            // y+2
            float d;
            d = V1 - V0; ys[0]  += d*d;
            d = V2 - V0; ys[1]  += d*d;
            d = V2 - V1; ys[2]  += d*d;
            d = V3 - V0; ys[3]  += d*d;
            d = V3 - V2; ys[4]  += d*d;
            d = V4 - V1; ys[5]  += d*d;
            d = V4 - V2; ys[6]  += d*d;
            d = V4 - V3; ys[7]  += d*d;
            d = V5 - V0; ys[8]  += d*d;
            d = V5 - V1; ys[9]  += d*d;
            d = V5 - V3; ys[10] += d*d;
            d = V5 - V4; ys[11] += d*d;
        }
        ysb[ty][x][0] = make_float4(ys[0], ys[1], ys[2],  ys[3]);
        ysb[ty][x][1] = make_float4(ys[4], ys[5], ys[6],  ys[7]);
        ysb[ty][x][2] = make_float4(ys[8], ys[9], ys[10], ys[11]);
        __syncthreads();

        // x-sum (x edge-clamped) via smem exchange
        float4 a0 = ysb[ty][xm1][0], b0 = ysb[ty][x][0], c0 = ysb[ty][xp1][0];
        float4 a1 = ysb[ty][xm1][1], b1 = ysb[ty][x][1], c1 = ysb[ty][xp1][1];
        float4 a2 = ysb[ty][xm1][2], b2 = ysb[ty][x][2], c2 = ysb[ty][xp1][2];

        float s[12];
        s[0] = a0.x+b0.x+c0.x; s[1] = a0.y+b0.y+c0.y;
        s[2] = a0.z+b0.z+c0.z; s[3] = a0.w+b0.w+c0.w;
        s[4] = a1.x+b1.x+c1.x; s[5] = a1.y+b1.y+c1.y;
        s[6] = a1.z+b1.z+c1.z; s[7] = a1.w+b1.w+c1.w;
        s[8] = a2.x+b2.x+c2.x; s[9] = a2.y+b2.y+c2.y;
        s[10]= a2.z+b2.z+c2.z; s[11]= a2.w+b2.w+c2.w;

        // rolling z window
        if (zp == zlo) {
            #pragma unroll
            for (int c = 0; c < 12; ++c) { prev[c] = s[c]; pair[c] = s[c] + s[c]; }
            // pair = 2*s only meaningful for z0==0 (virtual plane -1 == plane 0);
            // for z0>0 it is a placeholder never read before being overwritten.
        } else {
            const int zo = zp - 1;
            if (zo >= z0) emit(zo, pair, s, outBase, mvsum);
            #pragma unroll
            for (int c = 0; c < 12; ++c) { pair[c] = prev[c] + s[c]; prev[c] = s[c]; }
        }
    }
    if (z1 == 128) {
        // out(127): s(126)+s(127)+s(128), s(128)=s(127)  ->  pair + prev
        emit(127, pair, prev, outBase, mvsum);
    }

    // block-reduce mind_var partial sum
    red[lin] = mvsum;
    __syncthreads();
    for (int off = 128; off > 0; off >>= 1) {
        if (lin < off) red[lin] += red[lin + off];
        __syncthreads();
    }
    if (lin == 0) atomicAdd(&g_msum[t], red[0]);
}

__global__ __launch_bounds__(256)
void loss_kernel()
{
    // each thread handles 8 voxel-pairs; mind precomputed, mind_var at channel 12
    const unsigned i8 = blockIdx.x * 256u + threadIdx.x;   // 0 .. 2*NVOX/8-1
    const float mP = g_msum[0] * (1.f / 4194304.f);
    const float mT = g_msum[1] * (1.f / 4194304.f);

    const unsigned nn = i8 >> 18;                 // NVOX/8 = 2^18
    const unsigned s8 = i8 & ((NVOX / 8u) - 1u);

    const uint4* bp = (const uint4*)g_ssd + (size_t)nn       * 13u * (NVOX/8u) + s8;
    const uint4* bt = (const uint4*)g_ssd + (size_t)(2 + nn) * 13u * (NVOX/8u) + s8;

    uint4 vp[13], vt[13];
    #pragma unroll
    for (int c = 0; c < 13; ++c) vp[c] = bp[(size_t)c * (NVOX/8u)];
    #pragma unroll
    for (int c = 0; c < 13; ++c) vt[c] = bt[(size_t)c * (NVOX/8u)];

    const __half2* hp = (const __half2*)vp;   // hp[c*4 + j]
    const __half2* ht = (const __half2*)vt;

    const __half2 loP = __float2half2_rn(0.001f * mP);
    const __half2 hiP = __float2half2_rn(1000.f * mP);
    const __half2 loT = __float2half2_rn(0.001f * mT);
    const __half2 hiT = __float2half2_rn(1000.f * mT);

    float acc = 0.f;
    #pragma unroll
    for (int j = 0; j < 4; ++j) {
        __half2 mvP = __hmin2(__hmax2(hp[12*4 + j], loP), hiP);
        __half2 mvT = __hmin2(__hmax2(ht[12*4 + j], loT), hiT);
        __half2 nivP = __hneg2(h2rcp(mvP));
        __half2 nivT = __hneg2(h2rcp(mvT));
        #pragma unroll
        for (int c = 0; c < 12; ++c) {
            __half2 eP = h2exp(__hmul2(hp[c*4 + j], nivP));
            __half2 eT = h2exp(__hmul2(ht[c*4 + j], nivT));
            float2 d = __half22float2(__hsub2(eP, eT));
            acc += d.x * d.x + d.y * d.y;
        }
    }

    __shared__ float red[256];
    red[threadIdx.x] = acc;
    __syncthreads();
    for (int off = 128; off > 0; off >>= 1) {
        if (threadIdx.x < off) red[threadIdx.x] += red[threadIdx.x + off];
        __syncthreads();
    }
    if (threadIdx.x == 0) atomicAdd(&g_loss, red[0]);
}

__global__ void finish_kernel(float* __restrict__ out)
{
    out[0] = g_loss * (1.f / 50331648.f);
    // reset accumulators for the next graph replay
    g_loss = 0.f; g_msum[0] = 0.f; g_msum[1] = 0.f;
}

extern "C" void kernel_launch(void* const* d_in, const int* in_sizes, int n_in,
                              void* d_out, int out_size)
{
    const float* pred = (const float*)d_in[0];
    const float* targ = (const float*)d_in[1];

    ssd_kernel<<<dim3(64, 128 / CH, 4), dim3(128, 2)>>>(pred, targ);
    loss_kernel<<<2048, 256>>>();
    finish_kernel<<<1, 1>>>((float*)d_out);
}

// round 12
// speedup vs baseline: 1.2433x; 1.0824x over previous
#include <cuda_runtime.h>
#include <cuda_fp16.h>

#define NVOX 2097152u            // 128^3
#define PLANE 16384              // 128*128
#define CH 32                    // output z-planes per block (z-chunking)

// Scratch: [t*2+n][c(13)][z][y][x] fp16. c=0..11: mind = ssd - min; c=12: mind_var.
// 2*2*13*128^3 halfs = 218 MB
__device__ __half g_ssd[(size_t)2 * 2 * 13 * NVOX];
__device__ float g_msum[2] = {0.f, 0.f};   // finish_kernel re-zeroes after read
__device__ float g_loss = 0.f;

// emit outputs for plane zo given the two z-partial arrays (a + b = full 3-plane sum)
__device__ __forceinline__ void emit(int zo, const float* __restrict__ a,
                                     const float* __restrict__ b,
                                     __half* __restrict__ outBase, float& mvsum)
{
    float v[12];
    #pragma unroll
    for (int c = 0; c < 12; ++c) v[c] = (a[c] + b[c]) * (1.f / 27.f);
    float mn = fminf(fminf(fminf(v[0],v[1]),fminf(v[2],v[3])),
                     fminf(fminf(fminf(v[4],v[5]),fminf(v[6],v[7])),
                           fminf(fminf(v[8],v[9]),fminf(v[10],v[11]))));
    float sm = ((v[0]+v[1])+(v[2]+v[3])) + ((v[4]+v[5])+(v[6]+v[7]))
             + ((v[8]+v[9])+(v[10]+v[11]));
    float mv = sm * (1.f/12.f) - mn;
    __half* o = outBase + (size_t)zo * PLANE;
    #pragma unroll
    for (int c = 0; c < 12; ++c) o[(size_t)c * NVOX] = __float2half_rn(v[c] - mn);
    o[(size_t)12 * NVOX] = __float2half_rn(mv);
    mvsum += mv;
}

__global__ __launch_bounds__(256)
void ssd_kernel(const float* __restrict__ pred, const float* __restrict__ targ)
{
    const int x  = threadIdx.x;           // 0..127
    const int ty = threadIdx.y;           // 0..1
    const int y0 = blockIdx.x * 2;
    const int zc = blockIdx.y;            // z chunk
    const int tn = blockIdx.z;            // t*2+n
    const int t  = tn >> 1;
    const int n  = tn & 1;

    const int z0 = zc * CH, z1 = z0 + CH;
    const int zlo = max(z0 - 1, 0);
    const int zhi = min(z1, 127);

    const float* img = (t == 0 ? pred : targ) + (size_t)n * NVOX;
    __half* outBase = g_ssd + (size_t)tn * 13u * NVOX
                    + (size_t)(y0 + ty) * 128 + x;

    __shared__ float  simg[6][8][128];          // 24 KB, 6-slot z ring
    __shared__ float4 ysb[2][2][128][3];        // 24 KB, double-buffered exchange
    float* red = (float*)ysb;                   // reduction aliases ysb post-loop

    const int lin = ty * 128 + x;

    // preload planes zlo-2 .. zlo+2 (content z-clamped) into the ring
    for (int q = zlo - 2; q <= zlo + 2; ++q) {
        const int slot = (q + 12) % 6;
        const float* src = img + (size_t)min(max(q, 0), 127) * PLANE;
        #pragma unroll
        for (int k = 0; k < 4; ++k) {
            int e = lin + k * 256;
            int row = e >> 7, xx = e & 127;
            int gy = min(max(y0 - 3 + row, 0), 127);
            simg[slot][row][xx] = src[gy * 128 + xx];
        }
    }
    // prefetch plane zlo+3 into registers
    float pf[4];
    {
        const float* src = img + (size_t)min(zlo + 3, 127) * PLANE;
        #pragma unroll
        for (int k = 0; k < 4; ++k) {
            int e = lin + k * 256;
            int row = e >> 7, xx = e & 127;
            int gy = min(max(y0 - 3 + row, 0), 127);
            pf[k] = src[gy * 128 + xx];
        }
    }
    __syncthreads();

    const int xm1 = max(x - 1, 0), xp1 = min(x + 1, 127);
    const int gy0 = y0 + ty;

    // hoist all z-invariant clamped sample offsets (per dy = -1,0,1)
    int rA[3], rmA[3], rpA[3], rx2m[3], rx2p[3];
    {
        const int xm2 = max(x - 2, 0), xp2 = min(x + 2, 127);
        #pragma unroll
        for (int k = 0; k < 3; ++k) {
            int ly = min(max(gy0 + (k - 1), 0), 127);
            int base = (ly - y0 + 3) * 128;
            rA[k]   = base + x;
            rx2m[k] = base + xm2;
            rx2p[k] = base + xp2;
            rmA[k]  = (max(ly - 2, 0)   - y0 + 3) * 128 + x;
            rpA[k]  = (min(ly + 2, 127) - y0 + 3) * 128 + x;
        }
    }

    float prev[12], pair[12];             // s(zp-1), s(zp-2)+s(zp-1)
    float mvsum = 0.f;

    for (int zp = zlo; zp <= zhi; ++zp) {
        // ---- compute ys(zp) from ring (planes zp-2, zp, zp+2; staged earlier) ----
        const float* Pzm = &simg[(zp + 4) % 6][0][0];   // plane zp-2 (clamped)
        const float* Pzc = &simg[ zp      % 6][0][0];   // plane zp
        const float* Pzp = &simg[(zp + 2) % 6][0][0];   // plane zp+2 (clamped)

        float ys[12];
        #pragma unroll
        for (int c = 0; c < 12; ++c) ys[c] = 0.f;

        #pragma unroll
        for (int k = 0; k < 3; ++k) {
            float V0 = Pzm[rA[k]];      // z-2
            float V1 = Pzc[rx2m[k]];    // x-2
            float V2 = Pzc[rmA[k]];     // y-2
            float V3 = Pzc[rx2p[k]];    // x+2
            float V4 = Pzp[rA[k]];      // z+2
            float V5 = Pzc[rpA[k]];     // y+2
            float d;
            d = V1 - V0; ys[0]  += d*d;
            d = V2 - V0; ys[1]  += d*d;
            d = V2 - V1; ys[2]  += d*d;
            d = V3 - V0; ys[3]  += d*d;
            d = V3 - V2; ys[4]  += d*d;
            d = V4 - V1; ys[5]  += d*d;
            d = V4 - V2; ys[6]  += d*d;
            d = V4 - V3; ys[7]  += d*d;
            d = V5 - V0; ys[8]  += d*d;
            d = V5 - V1; ys[9]  += d*d;
            d = V5 - V3; ys[10] += d*d;
            d = V5 - V4; ys[11] += d*d;
        }

        // ---- publish ys (double-buffered) ----
        const int buf = zp & 1;
        ysb[buf][ty][x][0] = make_float4(ys[0], ys[1], ys[2],  ys[3]);
        ysb[buf][ty][x][1] = make_float4(ys[4], ys[5], ys[6],  ys[7]);
        ysb[buf][ty][x][2] = make_float4(ys[8], ys[9], ys[10], ys[11]);

        // ---- stage plane zp+3 from pf; prefetch plane zp+4 ----
        {
            const int slot = (zp + 3) % 6;
            #pragma unroll
            for (int k = 0; k < 4; ++k) {
                int e = lin + k * 256;
                int row = e >> 7, xx = e & 127;
                simg[slot][row][xx] = pf[k];
            }
        }
        {
            const float* src = img + (size_t)min(zp + 4, 127) * PLANE;
            #pragma unroll
            for (int k = 0; k < 4; ++k) {
                int e = lin + k * 256;
                int row = e >> 7, xx = e & 127;
                int gy = min(max(y0 - 3 + row, 0), 127);
                pf[k] = src[gy * 128 + xx];
            }
        }

        __syncthreads();   // single barrier per step

        // ---- x-sum: neighbors from smem, center from registers ----
        float4 a0 = ysb[buf][ty][xm1][0], c0 = ysb[buf][ty][xp1][0];
        float4 a1 = ysb[buf][ty][xm1][1], c1 = ysb[buf][ty][xp1][1];
        float4 a2 = ysb[buf][ty][xm1][2], c2 = ysb[buf][ty][xp1][2];

        float s[12];
        s[0] = a0.x+ys[0]+c0.x;  s[1] = a0.y+ys[1]+c0.y;
        s[2] = a0.z+ys[2]+c0.z;  s[3] = a0.w+ys[3]+c0.w;
        s[4] = a1.x+ys[4]+c1.x;  s[5] = a1.y+ys[5]+c1.y;
        s[6] = a1.z+ys[6]+c1.z;  s[7] = a1.w+ys[7]+c1.w;
        s[8] = a2.x+ys[8]+c2.x;  s[9] = a2.y+ys[9]+c2.y;
        s[10]= a2.z+ys[10]+c2.z; s[11]= a2.w+ys[11]+c2.w;

        // ---- rolling z window ----
        if (zp == zlo) {
            #pragma unroll
            for (int c = 0; c < 12; ++c) { prev[c] = s[c]; pair[c] = s[c] + s[c]; }
            // pair = 2*s only meaningful for z0==0 (virtual plane -1 == plane 0);
            // for z0>0 it is a placeholder never read before being overwritten.
        } else {
            const int zo = zp - 1;
            if (zo >= z0) emit(zo, pair, s, outBase, mvsum);
            #pragma unroll
            for (int c = 0; c < 12; ++c) { pair[c] = prev[c] + s[c]; prev[c] = s[c]; }
        }
    }
    if (z1 == 128) {
        // out(127): s(126)+s(127)+s(128), s(128)=s(127)  ->  pair + prev
        emit(127, pair, prev, outBase, mvsum);
    }

    // block-reduce mind_var partial sum (red aliases ysb — safe after loop)
    __syncthreads();
    red[lin] = mvsum;
    __syncthreads();
    for (int off = 128; off > 0; off >>= 1) {
        if (lin < off) red[lin] += red[lin + off];
        __syncthreads();
    }
    if (lin == 0) atomicAdd(&g_msum[t], red[0]);
}

__global__ __launch_bounds__(256)
void loss_kernel()
{
    // each thread handles 8 voxel-pairs; mind precomputed, mind_var at channel 12
    const unsigned i8 = blockIdx.x * 256u + threadIdx.x;   // 0 .. 2*NVOX/8-1
    const float mP = g_msum[0] * (1.f / 4194304.f);
    const float mT = g_msum[1] * (1.f / 4194304.f);

    const unsigned nn = i8 >> 18;                 // NVOX/8 = 2^18
    const unsigned s8 = i8 & ((NVOX / 8u) - 1u);

    const uint4* bp = (const uint4*)g_ssd + (size_t)nn       * 13u * (NVOX/8u) + s8;
    const uint4* bt = (const uint4*)g_ssd + (size_t)(2 + nn) * 13u * (NVOX/8u) + s8;

    uint4 vp[13], vt[13];
    #pragma unroll
    for (int c = 0; c < 13; ++c) vp[c] = bp[(size_t)c * (NVOX/8u)];
    #pragma unroll
    for (int c = 0; c < 13; ++c) vt[c] = bt[(size_t)c * (NVOX/8u)];

    const __half2* hp = (const __half2*)vp;   // hp[c*4 + j]
    const __half2* ht = (const __half2*)vt;

    const __half2 loP = __float2half2_rn(0.001f * mP);
    const __half2 hiP = __float2half2_rn(1000.f * mP);
    const __half2 loT = __float2half2_rn(0.001f * mT);
    const __half2 hiT = __float2half2_rn(1000.f * mT);

    float acc = 0.f;
    #pragma unroll
    for (int j = 0; j < 4; ++j) {
        __half2 mvP = __hmin2(__hmax2(hp[12*4 + j], loP), hiP);
        __half2 mvT = __hmin2(__hmax2(ht[12*4 + j], loT), hiT);
        __half2 nivP = __hneg2(h2rcp(mvP));
        __half2 nivT = __hneg2(h2rcp(mvT));
        #pragma unroll
        for (int c = 0; c < 12; ++c) {
            __half2 eP = h2exp(__hmul2(hp[c*4 + j], nivP));
            __half2 eT = h2exp(__hmul2(ht[c*4 + j], nivT));
            float2 d = __half22float2(__hsub2(eP, eT));
            acc += d.x * d.x + d.y * d.y;
        }
    }

    __shared__ float red[256];
    red[threadIdx.x] = acc;
    __syncthreads();
    for (int off = 128; off > 0; off >>= 1) {
        if (threadIdx.x < off) red[threadIdx.x] += red[threadIdx.x + off];
        __syncthreads();
    }
    if (threadIdx.x == 0) atomicAdd(&g_loss, red[0]);
}

__global__ void finish_kernel(float* __restrict__ out)
{
    out[0] = g_loss * (1.f / 50331648.f);
    // reset accumulators for the next graph replay
    g_loss = 0.f; g_msum[0] = 0.f; g_msum[1] = 0.f;
}

extern "C" void kernel_launch(void* const* d_in, const int* in_sizes, int n_in,
                              void* d_out, int out_size)
{
    const float* pred = (const float*)d_in[0];
    const float* targ = (const float*)d_in[1];

    ssd_kernel<<<dim3(64, 128 / CH, 4), dim3(128, 2)>>>(pred, targ);
    loss_kernel<<<2048, 256>>>();
    finish_kernel<<<1, 1>>>((float*)d_out);
}

// round 13
// speedup vs baseline: 1.3383x; 1.0764x over previous
#include <cuda_runtime.h>
#include <cuda_fp16.h>

#define NVOX 2097152u            // 128^3
#define PLANE 16384              // 128*128
#define CH 32                    // output z-planes per block (z-chunking)

// Scratch, fp16, 218 MB total:
//   pair region: [tn][p(6)][z][y][x] as half2, pair p = channels (2p, 2p+1) of mind
//   mv   region: [tn][z][y][x] as half  (mind_var), at half-offset 48*NVOX
__device__ __half g_ssd[(size_t)52 * NVOX];
__device__ float g_msum[2] = {0.f, 0.f};   // finish_kernel re-zeroes after read
__device__ float g_loss = 0.f;

// emit outputs for plane zo. a+b = full 3-plane z sum (unnormalized: no 1/27 —
// the scale cancels exactly in exp(-mind/mind_var) and in the clip bounds).
__device__ __forceinline__ void emit(int zo, const float* __restrict__ a,
                                     const float* __restrict__ b,
                                     __half2* __restrict__ outV,
                                     __half*  __restrict__ outM, float& mvsum)
{
    float v[12];
    #pragma unroll
    for (int c = 0; c < 12; ++c) v[c] = a[c] + b[c];
    float mn = fminf(fminf(fminf(v[0],v[1]),fminf(v[2],v[3])),
                     fminf(fminf(fminf(v[4],v[5]),fminf(v[6],v[7])),
                           fminf(fminf(v[8],v[9]),fminf(v[10],v[11]))));
    float sm = ((v[0]+v[1])+(v[2]+v[3])) + ((v[4]+v[5])+(v[6]+v[7]))
             + ((v[8]+v[9])+(v[10]+v[11]));
    float mv = sm * (1.f/12.f) - mn;
    __half2* ov = outV + (size_t)zo * PLANE;
    #pragma unroll
    for (int p = 0; p < 6; ++p)
        ov[(size_t)p * NVOX] = __floats2half2_rn(v[2*p] - mn, v[2*p+1] - mn);
    outM[(size_t)zo * PLANE] = __float2half_rn(mv);
    mvsum += mv;
}

__global__ __launch_bounds__(256)
void ssd_kernel(const float* __restrict__ pred, const float* __restrict__ targ)
{
    const int x  = threadIdx.x;           // 0..127
    const int ty = threadIdx.y;           // 0..1
    const int y0 = blockIdx.x * 2;
    const int zc = blockIdx.y;            // z chunk
    const int tn = blockIdx.z;            // t*2+n
    const int t  = tn >> 1;
    const int n  = tn & 1;

    const int z0 = zc * CH, z1 = z0 + CH;
    const int zlo = max(z0 - 1, 0);
    const int zhi = min(z1, 127);

    const float* img = (t == 0 ? pred : targ) + (size_t)n * NVOX;
    const unsigned vox0 = (unsigned)(y0 + ty) * 128u + (unsigned)x;
    __half2* outV = (__half2*)g_ssd + (size_t)tn * 6u * NVOX + vox0;
    __half*  outM = g_ssd + (size_t)48 * NVOX + (size_t)tn * NVOX + vox0;

    __shared__ float  simg[6][8][128];          // 24 KB, 6-slot z ring
    __shared__ float4 ysb[2][2][128][3];        // 24 KB, double-buffered exchange
    float* red = (float*)ysb;                   // reduction aliases ysb post-loop

    const int lin = ty * 128 + x;

    // z-invariant staging offsets
    int sofs[4], gofs[4];
    #pragma unroll
    for (int k = 0; k < 4; ++k) {
        int e = lin + k * 256;
        int row = e >> 7, xx = e & 127;
        int gy = min(max(y0 - 3 + row, 0), 127);
        sofs[k] = row * 128 + xx;
        gofs[k] = gy * 128 + xx;
    }

    // preload planes zlo-2 .. zlo+2 (content z-clamped) into the ring
    for (int q = zlo - 2; q <= zlo + 2; ++q) {
        const int slot = (q + 12) % 6;
        const float* src = img + (size_t)min(max(q, 0), 127) * PLANE;
        #pragma unroll
        for (int k = 0; k < 4; ++k) simg[slot][0][sofs[k]] = src[gofs[k]];
    }
    // prefetch plane zlo+3 into registers
    float pf[4];
    {
        const float* src = img + (size_t)min(zlo + 3, 127) * PLANE;
        #pragma unroll
        for (int k = 0; k < 4; ++k) pf[k] = src[gofs[k]];
    }
    __syncthreads();

    const int xm1 = max(x - 1, 0), xp1 = min(x + 1, 127);
    const int gy0 = y0 + ty;

    // hoist all z-invariant clamped sample offsets (per dy = -1,0,1)
    int rA[3], rmA[3], rpA[3], rx2m[3], rx2p[3];
    {
        const int xm2 = max(x - 2, 0), xp2 = min(x + 2, 127);
        #pragma unroll
        for (int k = 0; k < 3; ++k) {
            int ly = min(max(gy0 + (k - 1), 0), 127);
            int base = (ly - y0 + 3) * 128;
            rA[k]   = base + x;
            rx2m[k] = base + xm2;
            rx2p[k] = base + xp2;
            rmA[k]  = (max(ly - 2, 0)   - y0 + 3) * 128 + x;
            rpA[k]  = (min(ly + 2, 127) - y0 + 3) * 128 + x;
        }
    }

    float prev[12], pair[12];             // s(zp-1), s(zp-2)+s(zp-1)
    float mvsum = 0.f;

    for (int zp = zlo; zp <= zhi; ++zp) {
        // ---- compute ys(zp) from ring (planes zp-2, zp, zp+2) ----
        const float* Pzm = &simg[(zp + 4) % 6][0][0];   // plane zp-2 (clamped)
        const float* Pzc = &simg[ zp      % 6][0][0];   // plane zp
        const float* Pzp = &simg[(zp + 2) % 6][0][0];   // plane zp+2 (clamped)

        float ys[12];
        #pragma unroll
        for (int c = 0; c < 12; ++c) ys[c] = 0.f;

        #pragma unroll
        for (int k = 0; k < 3; ++k) {
            float V0 = Pzm[rA[k]];      // z-2
            float V1 = Pzc[rx2m[k]];    // x-2
            float V2 = Pzc[rmA[k]];     // y-2
            float V3 = Pzc[rx2p[k]];    // x+2
            float V4 = Pzp[rA[k]];      // z+2
            float V5 = Pzc[rpA[k]];     // y+2
            float d;
            d = V1 - V0; ys[0]  += d*d;
            d = V2 - V0; ys[1]  += d*d;
            d = V2 - V1; ys[2]  += d*d;
            d = V3 - V0; ys[3]  += d*d;
            d = V3 - V2; ys[4]  += d*d;
            d = V4 - V1; ys[5]  += d*d;
            d = V4 - V2; ys[6]  += d*d;
            d = V4 - V3; ys[7]  += d*d;
            d = V5 - V0; ys[8]  += d*d;
            d = V5 - V1; ys[9]  += d*d;
            d = V5 - V3; ys[10] += d*d;
            d = V5 - V4; ys[11] += d*d;
        }

        // ---- publish ys (double-buffered) ----
        const int buf = zp & 1;
        ysb[buf][ty][x][0] = make_float4(ys[0], ys[1], ys[2],  ys[3]);
        ysb[buf][ty][x][1] = make_float4(ys[4], ys[5], ys[6],  ys[7]);
        ysb[buf][ty][x][2] = make_float4(ys[8], ys[9], ys[10], ys[11]);

        // ---- stage plane zp+3 from pf; prefetch plane zp+4 ----
        {
            const int slot = (zp + 3) % 6;
            #pragma unroll
            for (int k = 0; k < 4; ++k) simg[slot][0][sofs[k]] = pf[k];
        }
        {
            const float* src = img + (size_t)min(zp + 4, 127) * PLANE;
            #pragma unroll
            for (int k = 0; k < 4; ++k) pf[k] = src[gofs[k]];
        }

        __syncthreads();   // single barrier per step

        // ---- x-sum: neighbors from smem, center from registers ----
        float4 a0 = ysb[buf][ty][xm1][0], c0 = ysb[buf][ty][xp1][0];
        float4 a1 = ysb[buf][ty][xm1][1], c1 = ysb[buf][ty][xp1][1];
        float4 a2 = ysb[buf][ty][xm1][2], c2 = ysb[buf][ty][xp1][2];

        float s[12];
        s[0] = a0.x+ys[0]+c0.x;  s[1] = a0.y+ys[1]+c0.y;
        s[2] = a0.z+ys[2]+c0.z;  s[3] = a0.w+ys[3]+c0.w;
        s[4] = a1.x+ys[4]+c1.x;  s[5] = a1.y+ys[5]+c1.y;
        s[6] = a1.z+ys[6]+c1.z;  s[7] = a1.w+ys[7]+c1.w;
        s[8] = a2.x+ys[8]+c2.x;  s[9] = a2.y+ys[9]+c2.y;
        s[10]= a2.z+ys[10]+c2.z; s[11]= a2.w+ys[11]+c2.w;

        // ---- rolling z window ----
        if (zp == zlo) {
            #pragma unroll
            for (int c = 0; c < 12; ++c) { prev[c] = s[c]; pair[c] = s[c] + s[c]; }
            // pair = 2*s only meaningful for z0==0 (virtual plane -1 == plane 0);
            // for z0>0 it is a placeholder never read before being overwritten.
        } else {
            const int zo = zp - 1;
            if (zo >= z0) emit(zo, pair, s, outV, outM, mvsum);
            #pragma unroll
            for (int c = 0; c < 12; ++c) { pair[c] = prev[c] + s[c]; prev[c] = s[c]; }
        }
    }
    if (z1 == 128) {
        // out(127): s(126)+s(127)+s(128), s(128)=s(127)  ->  pair + prev
        emit(127, pair, prev, outV, outM, mvsum);
    }

    // block-reduce mind_var partial sum (red aliases ysb — safe after loop)
    __syncthreads();
    red[lin] = mvsum;
    __syncthreads();
    for (int off = 128; off > 0; off >>= 1) {
        if (lin < off) red[lin] += red[lin + off];
        __syncthreads();
    }
    if (lin == 0) atomicAdd(&g_msum[t], red[0]);
}

__global__ __launch_bounds__(256)
void loss_kernel()
{
    // each thread handles 4 voxel-pairs (pred+targ); pair-interleaved mind layout
    const unsigned i4 = blockIdx.x * 256u + threadIdx.x;   // 0 .. 2*NVOX/4-1
    const float mP = g_msum[0] * (1.f / 4194304.f);
    const float mT = g_msum[1] * (1.f / 4194304.f);

    const unsigned v4 = i4 * 4u;                  // first voxel (global over n,z,y,x)
    const unsigned nn = v4 >> 21;                 // batch index
    const unsigned s  = v4 & (NVOX - 1u);         // voxel within volume
    const unsigned sq = s >> 2;                   // uint4 index

    const unsigned tnP = nn, tnT = 2u + nn;

    // v-pair loads: 6 uint4 each = 4 voxels x half2(pair)
    uint4 vp[6], vt[6];
    #pragma unroll
    for (int p = 0; p < 6; ++p) {
        vp[p] = ((const uint4*)((const __half2*)g_ssd + (size_t)(tnP*6 + p) * NVOX))[sq];
        vt[p] = ((const uint4*)((const __half2*)g_ssd + (size_t)(tnT*6 + p) * NVOX))[sq];
    }
    // mv loads: 4 halfs each
    uint2 mvPu = ((const uint2*)(g_ssd + (size_t)48 * NVOX + (size_t)tnP * NVOX))[sq];
    uint2 mvTu = ((const uint2*)(g_ssd + (size_t)48 * NVOX + (size_t)tnT * NVOX))[sq];

    const __half* mvPh = (const __half*)&mvPu;
    const __half* mvTh = (const __half*)&mvTu;
    const __half2* hp = (const __half2*)vp;   // hp[p*4 + j] = pair p, voxel j
    const __half2* ht = (const __half2*)vt;

    float acc = 0.f;
    #pragma unroll
    for (int j = 0; j < 4; ++j) {
        float fmvP = __half2float(mvPh[j]);
        float fmvT = __half2float(mvTh[j]);
        fmvP = fminf(fmaxf(fmvP, 0.001f * mP), 1000.f * mP);
        fmvT = fminf(fmaxf(fmvT, 0.001f * mT), 1000.f * mT);
        __half2 nivP = __float2half2_rn(-1.f / fmvP);
        __half2 nivT = __float2half2_rn(-1.f / fmvT);
        #pragma unroll
        for (int p = 0; p < 6; ++p) {
            __half2 eP = h2exp(__hmul2(hp[p*4 + j], nivP));
            __half2 eT = h2exp(__hmul2(ht[p*4 + j], nivT));
            float2 d = __half22float2(__hsub2(eP, eT));
            acc += d.x * d.x + d.y * d.y;
        }
    }

    __shared__ float red[256];
    red[threadIdx.x] = acc;
    __syncthreads();
    for (int off = 128; off > 0; off >>= 1) {
        if (threadIdx.x < off) red[threadIdx.x] += red[threadIdx.x + off];
        __syncthreads();
    }
    if (threadIdx.x == 0) atomicAdd(&g_loss, red[0]);
}

__global__ void finish_kernel(float* __restrict__ out)
{
    out[0] = g_loss * (1.f / 50331648.f);
    // reset accumulators for the next graph replay
    g_loss = 0.f; g_msum[0] = 0.f; g_msum[1] = 0.f;
}

extern "C" void kernel_launch(void* const* d_in, const int* in_sizes, int n_in,
                              void* d_out, int out_size)
{
    const float* pred = (const float*)d_in[0];
    const float* targ = (const float*)d_in[1];

    ssd_kernel<<<dim3(64, 128 / CH, 4), dim3(128, 2)>>>(pred, targ);
    loss_kernel<<<4096, 256>>>();
    finish_kernel<<<1, 1>>>((float*)d_out);
}

// round 14
// speedup vs baseline: 1.5096x; 1.1280x over previous
#include <cuda_runtime.h>
#include <cuda_fp16.h>

#define NVOX 2097152u            // 128^3
#define PLANE 16384              // 128*128
#define CH 32                    // output z-planes per block

// Scratch, fp16, 218 MB: mind channel-planar [tn][c(12)][z][y][x] halves,
// mind_var at half-offset 48*NVOX: [tn][z][y][x].
__device__ __half g_ssd[(size_t)52 * NVOX];
__device__ float g_msum[2] = {0.f, 0.f};
__device__ float g_loss = 0.f;

__device__ __forceinline__ unsigned h2u(__half2 h) { return *reinterpret_cast<unsigned*>(&h); }
__device__ __forceinline__ __half2  u2h(unsigned u) { return *reinterpret_cast<__half2*>(&u); }

// emit plane zo for 2 voxels (half2 lanes = columns a,b). a+b partials in half2.
__device__ __forceinline__ void emit(int zo, const __half2* __restrict__ pa,
                                     const __half2* __restrict__ pb,
                                     __half* __restrict__ outC,
                                     __half* __restrict__ outM, float& mvsum)
{
    __half2 v[12];
    #pragma unroll
    for (int c = 0; c < 12; ++c) v[c] = __hadd2(pa[c], pb[c]);
    __half2 mn = v[0], sm = v[0];
    #pragma unroll
    for (int c = 1; c < 12; ++c) { mn = __hmin2(mn, v[c]); sm = __hadd2(sm, v[c]); }
    const __half2 k12 = __float2half2_rn(1.f / 12.f);
    __half2 mv = __hfma2(sm, k12, __hneg2(mn));
    __half* oz = outC + (size_t)zo * PLANE;
    #pragma unroll
    for (int c = 0; c < 12; ++c)
        *reinterpret_cast<__half2*>(oz + (size_t)c * NVOX) = __hsub2(v[c], mn);
    *reinterpret_cast<__half2*>(outM + (size_t)zo * PLANE) = mv;
    float2 f = __half22float2(mv);
    mvsum += f.x + f.y;
}

__global__ __launch_bounds__(256)
void ssd_kernel(const float* __restrict__ pred, const float* __restrict__ targ)
{
    const int tx = threadIdx.x;           // 0..63, columns (2tx, 2tx+1)
    const int ty = threadIdx.y;           // 0..3
    const int y0 = blockIdx.x * 4;
    const int zc = blockIdx.y;
    const int tn = blockIdx.z;
    const int t  = tn >> 1;
    const int n  = tn & 1;

    const int z0 = zc * CH, z1 = z0 + CH;
    const int zlo = max(z0 - 1, 0);
    const int zhi = min(z1, 127);

    const float* img = (t == 0 ? pred : targ) + (size_t)n * NVOX;
    const unsigned vox0 = (unsigned)(y0 + ty) * 128u + (unsigned)(2 * tx);
    __half* outC = g_ssd + (size_t)tn * 12u * NVOX + vox0;
    __half* outM = g_ssd + (size_t)48 * NVOX + (size_t)tn * NVOX + vox0;

    __shared__ __half simg[6][10][128];          // 15 KB, fp16 image ring
    __shared__ uint4  ysbE4[2][4][64];           // even cols, ch 0..7
    __shared__ uint2  ysbE2[2][4][64];           // even cols, ch 8..11
    __shared__ uint4  ysbO4[2][4][64];           // odd  cols, ch 0..7
    __shared__ uint2  ysbO2[2][4][64];           // odd  cols, ch 8..11
    __shared__ float  red[256];

    const int lin = ty * 64 + tx;

    // staging offsets: plane = 10 rows x 64 half2
    int sofs[3], gofs[3];
    #pragma unroll
    for (int k = 0; k < 3; ++k) {
        int j = lin + k * 256;
        int row = j >> 6, cp = j & 63;
        int gy = min(max(y0 - 3 + row, 0), 127);
        sofs[k] = j;
        gofs[k] = gy * 64 + cp;
    }
    const bool sv2 = lin < 128;   // k=2 valid only for first 128 threads (640 half2)

    // preload planes zlo-2 .. zlo+2
    for (int q = zlo - 2; q <= zlo + 2; ++q) {
        const int slot = (q + 12) % 6;
        const float2* src = (const float2*)(img + (size_t)min(max(q, 0), 127) * PLANE);
        __half2* S = (__half2*)&simg[slot][0][0];
        S[sofs[0]] = __float22half2_rn(src[gofs[0]]);
        S[sofs[1]] = __float22half2_rn(src[gofs[1]]);
        if (sv2) S[sofs[2]] = __float22half2_rn(src[gofs[2]]);
    }
    // prefetch plane zlo+3
    float2 pf[3];
    {
        const float2* src = (const float2*)(img + (size_t)min(zlo + 3, 127) * PLANE);
        pf[0] = src[gofs[0]];
        pf[1] = src[gofs[1]];
        if (sv2) pf[2] = src[gofs[2]];
    }
    __syncthreads();

    const int gy0 = y0 + ty;
    const bool atL = (tx == 0), atR = (tx == 63);
    const int txm = max(tx - 1, 0), txp = min(tx + 1, 63);

    // hoist z-invariant sample offsets (half2 indices; per dy = -1,0,1)
    int rA[3], rmA[3], rpA[3], rxm[3], rxp[3];
    #pragma unroll
    for (int k = 0; k < 3; ++k) {
        int ly = min(max(gy0 + (k - 1), 0), 127);
        int rowc = ly - y0 + 3;
        rA[k]  = rowc * 64 + tx;
        rxm[k] = rowc * 64 + txm;
        rxp[k] = rowc * 64 + txp;
        rmA[k] = (max(ly - 2, 0)   - y0 + 3) * 64 + tx;
        rpA[k] = (min(ly + 2, 127) - y0 + 3) * 64 + tx;
    }

    __half2 prev[12], pair[12];
    float mvsum = 0.f;

    for (int zp = zlo; zp <= zhi; ++zp) {
        const __half2* Pzm = (const __half2*)&simg[(zp + 4) % 6][0][0];  // z-2
        const __half2* Pzc = (const __half2*)&simg[ zp      % 6][0][0];  // z
        const __half2* Pzp = (const __half2*)&simg[(zp + 2) % 6][0][0];  // z+2

        __half2 ys[12];
        #pragma unroll
        for (int c = 0; c < 12; ++c) ys[c] = __float2half2_rn(0.f);

        #pragma unroll
        for (int k = 0; k < 3; ++k) {
            __half2 V0 = Pzm[rA[k]];      // z-2
            __half2 V1 = Pzc[rxm[k]];     // x-2 pair
            __half2 V2 = Pzc[rmA[k]];     // y-2
            __half2 V3 = Pzc[rxp[k]];     // x+2 pair
            __half2 V4 = Pzp[rA[k]];      // z+2
            __half2 V5 = Pzc[rpA[k]];     // y+2
            if (atL) V1 = __half2half2(__low2half(V1));    // x clamp at 0
            if (atR) V3 = __half2half2(__high2half(V3));   // x clamp at 127
            __half2 d;
            d = __hsub2(V1, V0); ys[0]  = __hfma2(d, d, ys[0]);
            d = __hsub2(V2, V0); ys[1]  = __hfma2(d, d, ys[1]);
            d = __hsub2(V2, V1); ys[2]  = __hfma2(d, d, ys[2]);
            d = __hsub2(V3, V0); ys[3]  = __hfma2(d, d, ys[3]);
            d = __hsub2(V3, V2); ys[4]  = __hfma2(d, d, ys[4]);
            d = __hsub2(V4, V1); ys[5]  = __hfma2(d, d, ys[5]);
            d = __hsub2(V4, V2); ys[6]  = __hfma2(d, d, ys[6]);
            d = __hsub2(V4, V3); ys[7]  = __hfma2(d, d, ys[7]);
            d = __hsub2(V5, V0); ys[8]  = __hfma2(d, d, ys[8]);
            d = __hsub2(V5, V1); ys[9]  = __hfma2(d, d, ys[9]);
            d = __hsub2(V5, V3); ys[10] = __hfma2(d, d, ys[10]);
            d = __hsub2(V5, V4); ys[11] = __hfma2(d, d, ys[11]);
        }

        // publish: deinterleave even/odd columns, channel-paired half2s
        const int buf = zp & 1;
        {
            __half2 e0 = __lows2half2 (ys[0], ys[1]),  e1 = __lows2half2 (ys[2], ys[3]);
            __half2 e2 = __lows2half2 (ys[4], ys[5]),  e3 = __lows2half2 (ys[6], ys[7]);
            __half2 e4 = __lows2half2 (ys[8], ys[9]),  e5 = __lows2half2 (ys[10], ys[11]);
            __half2 o0 = __highs2half2(ys[0], ys[1]),  o1 = __highs2half2(ys[2], ys[3]);
            __half2 o2 = __highs2half2(ys[4], ys[5]),  o3 = __highs2half2(ys[6], ys[7]);
            __half2 o4 = __highs2half2(ys[8], ys[9]),  o5 = __highs2half2(ys[10], ys[11]);
            ysbE4[buf][ty][tx] = make_uint4(h2u(e0), h2u(e1), h2u(e2), h2u(e3));
            ysbE2[buf][ty][tx] = make_uint2(h2u(e4), h2u(e5));
            ysbO4[buf][ty][tx] = make_uint4(h2u(o0), h2u(o1), h2u(o2), h2u(o3));
            ysbO2[buf][ty][tx] = make_uint2(h2u(o4), h2u(o5));
        }

        // stage plane zp+3; prefetch zp+4
        {
            __half2* S = (__half2*)&simg[(zp + 3) % 6][0][0];
            S[sofs[0]] = __float22half2_rn(pf[0]);
            S[sofs[1]] = __float22half2_rn(pf[1]);
            if (sv2) S[sofs[2]] = __float22half2_rn(pf[2]);
            const float2* src = (const float2*)(img + (size_t)min(zp + 4, 127) * PLANE);
            pf[0] = src[gofs[0]];
            pf[1] = src[gofs[1]];
            if (sv2) pf[2] = src[gofs[2]];
        }

        __syncthreads();

        // neighbor columns: left's odd col = my a-1; right's even col = my b+1
        uint4 L4 = ysbO4[buf][ty][txm]; uint2 L2 = ysbO2[buf][ty][txm];
        uint4 R4 = ysbE4[buf][ty][txp]; uint2 R2 = ysbE2[buf][ty][txp];
        __half2 Lp[6] = {u2h(L4.x), u2h(L4.y), u2h(L4.z), u2h(L4.w), u2h(L2.x), u2h(L2.y)};
        __half2 Rp[6] = {u2h(R4.x), u2h(R4.y), u2h(R4.z), u2h(R4.w), u2h(R2.x), u2h(R2.y)};

        __half2 s[12];
        #pragma unroll
        for (int p = 0; p < 6; ++p) {
            __half2 mixe = __lows2half2 (Lp[p], Rp[p]);   // (L_{2p},   R_{2p})
            __half2 mixo = __highs2half2(Lp[p], Rp[p]);   // (L_{2p+1}, R_{2p+1})
            if (atL) {
                mixe = __halves2half2(__low2half(ys[2*p]),   __high2half(mixe));
                mixo = __halves2half2(__low2half(ys[2*p+1]), __high2half(mixo));
            }
            if (atR) {
                mixe = __halves2half2(__low2half(mixe), __high2half(ys[2*p]));
                mixo = __halves2half2(__low2half(mixo), __high2half(ys[2*p+1]));
            }
            __half2 me = __hadd2(ys[2*p],   __lowhigh2highlow(ys[2*p]));
            __half2 mo = __hadd2(ys[2*p+1], __lowhigh2highlow(ys[2*p+1]));
            s[2*p]   = __hadd2(me, mixe);
            s[2*p+1] = __hadd2(mo, mixo);
        }

        // rolling z window
        if (zp == zlo) {
            #pragma unroll
            for (int c = 0; c < 12; ++c) { prev[c] = s[c]; pair[c] = __hadd2(s[c], s[c]); }
            // pair=2s only used when z0==0 (virtual plane -1 == plane 0)
        } else {
            const int zo = zp - 1;
            if (zo >= z0) emit(zo, pair, s, outC, outM, mvsum);
            #pragma unroll
            for (int c = 0; c < 12; ++c) { pair[c] = __hadd2(prev[c], s[c]); prev[c] = s[c]; }
        }
    }
    if (z1 == 128) emit(127, pair, prev, outC, outM, mvsum);

    // block-reduce mind_var partial sum
    red[lin] = mvsum;
    __syncthreads();
    for (int off = 128; off > 0; off >>= 1) {
        if (lin < off) red[lin] += red[lin + off];
        __syncthreads();
    }
    if (lin == 0) atomicAdd(&g_msum[t], red[0]);
}

__global__ __launch_bounds__(256)
void loss_kernel()
{
    // 8 voxels per thread; channel-planar half layout
    const unsigned i8 = blockIdx.x * 256u + threadIdx.x;   // 0 .. 2*NVOX/8-1
    const float mP = g_msum[0] * (1.f / 4194304.f);
    const float mT = g_msum[1] * (1.f / 4194304.f);

    const unsigned v8 = i8 * 8u;
    const unsigned nn = v8 >> 21;
    const unsigned s  = v8 & (NVOX - 1u);
    const unsigned q  = s >> 3;                   // uint4 index (8 halfs)

    const unsigned tnP = nn, tnT = 2u + nn;

    // mind_var for 8 voxels each
    uint4 mvPu = ((const uint4*)(g_ssd + (size_t)48 * NVOX + (size_t)tnP * NVOX))[q];
    uint4 mvTu = ((const uint4*)(g_ssd + (size_t)48 * NVOX + (size_t)tnT * NVOX))[q];
    const __half* mvPh = (const __half*)&mvPu;
    const __half* mvTh = (const __half*)&mvTu;

    __half2 nivP[4], nivT[4];
    #pragma unroll
    for (int j = 0; j < 4; ++j) {
        float a0 = fminf(fmaxf(__half2float(mvPh[2*j]),   0.001f * mP), 1000.f * mP);
        float a1 = fminf(fmaxf(__half2float(mvPh[2*j+1]), 0.001f * mP), 1000.f * mP);
        float b0 = fminf(fmaxf(__half2float(mvTh[2*j]),   0.001f * mT), 1000.f * mT);
        float b1 = fminf(fmaxf(__half2float(mvTh[2*j+1]), 0.001f * mT), 1000.f * mT);
        nivP[j] = __floats2half2_rn(-1.f / a0, -1.f / a1);
        nivT[j] = __floats2half2_rn(-1.f / b0, -1.f / b1);
    }

    float acc = 0.f;
    #pragma unroll
    for (int c = 0; c < 12; ++c) {
        uint4 mp = ((const uint4*)(g_ssd + (size_t)(tnP * 12u + c) * NVOX))[q];
        uint4 mt = ((const uint4*)(g_ssd + (size_t)(tnT * 12u + c) * NVOX))[q];
        const __half2* hp = (const __half2*)&mp;
        const __half2* ht = (const __half2*)&mt;
        #pragma unroll
        for (int j = 0; j < 4; ++j) {
            __half2 eP = h2exp(__hmul2(hp[j], nivP[j]));
            __half2 eT = h2exp(__hmul2(ht[j], nivT[j]));
            float2 d = __half22float2(__hsub2(eP, eT));
            acc += d.x * d.x + d.y * d.y;
        }
    }

    __shared__ float red[256];
    red[threadIdx.x] = acc;
    __syncthreads();
    for (int off = 128; off > 0; off >>= 1) {
        if (threadIdx.x < off) red[threadIdx.x] += red[threadIdx.x + off];
        __syncthreads();
    }
    if (threadIdx.x == 0) atomicAdd(&g_loss, red[0]);
}

__global__ void finish_kernel(float* __restrict__ out)
{
    out[0] = g_loss * (1.f / 50331648.f);
    g_loss = 0.f; g_msum[0] = 0.f; g_msum[1] = 0.f;
}

extern "C" void kernel_launch(void* const* d_in, const int* in_sizes, int n_in,
                              void* d_out, int out_size)
{
    const float* pred = (const float*)d_in[0];
    const float* targ = (const float*)d_in[1];

    ssd_kernel<<<dim3(32, 128 / CH, 4), dim3(64, 4)>>>(pred, targ);
    loss_kernel<<<2048, 256>>>();
    finish_kernel<<<1, 1>>>((float*)d_out);
}